// round 7
// baseline (speedup 1.0000x reference)
#include <cuda_runtime.h>
#include <cuda_bf16.h>
#include <stdint.h>

#define NG 4096
#define NPL 512
#define BB 64
#define SS 128
#define KC 32

#define KSPLIT 8
#define KSEG (NG / KSPLIT)          // 512
#define STEP_CHUNKS (KSEG / KC)     // 16
#define DEC_CHUNKS (NG / KC)        // 128

#define PADW 40                      // bf16 elems -> 80B row stride (conflict-free ldmatrix)
#define A_BYTES (64 * PADW * 2)      // 5120
#define B_BYTES (128 * PADW * 2)     // 10240
#define STAGE_BYTES (2 * A_BYTES + 2 * B_BYTES)   // 30720
#define NSTAGE 3
#define SMEM_BYTES (NSTAGE * STAGE_BYTES)         // 92160

__device__ __nv_bfloat16 g_Whh_hi[(size_t)NG * NG];
__device__ __nv_bfloat16 g_Whh_lo[(size_t)NG * NG];
__device__ __nv_bfloat16 g_Wdec_hi[(size_t)NPL * NG];
__device__ __nv_bfloat16 g_Wdec_lo[(size_t)NPL * NG];
__device__ __nv_bfloat16 g_h0_hi[BB * NG];
__device__ __nv_bfloat16 g_h0_lo[BB * NG];
// hs layout: [b][t][g]
__device__ __nv_bfloat16 g_hs_hi[(size_t)BB * SS * NG];
__device__ __nv_bfloat16 g_hs_lo[(size_t)BB * SS * NG];
__device__ float g_part[(size_t)32 * KSPLIT * 64 * 128];   // [n][kq][b][g]
__device__ unsigned int g_cnt[32];

// ---------------- PTX helpers ----------------
__device__ __forceinline__ uint32_t smem_u32(const void* p) {
    return (uint32_t)__cvta_generic_to_shared(p);
}
__device__ __forceinline__ uint64_t pol_evict_last() {
    uint64_t p; asm("createpolicy.fractional.L2::evict_last.b64 %0, 1.0;" : "=l"(p)); return p;
}
__device__ __forceinline__ uint64_t pol_evict_first() {
    uint64_t p; asm("createpolicy.fractional.L2::evict_first.b64 %0, 1.0;" : "=l"(p)); return p;
}
__device__ __forceinline__ void cp16p(uint32_t dst, const void* src, uint64_t pol) {
    asm volatile("cp.async.cg.shared.global.L2::cache_hint [%0], [%1], 16, %2;\n"
                 :: "r"(dst), "l"(src), "l"(pol));
}
__device__ __forceinline__ void cp_commit() {
    asm volatile("cp.async.commit_group;\n" ::: "memory");
}
template<int N>
__device__ __forceinline__ void cp_wait() {
    asm volatile("cp.async.wait_group %0;\n" :: "n"(N) : "memory");
}
__device__ __forceinline__ void ldm_x4(uint32_t a, uint32_t& r0, uint32_t& r1,
                                       uint32_t& r2, uint32_t& r3) {
    asm volatile("ldmatrix.sync.aligned.m8n8.x4.shared.b16 {%0,%1,%2,%3}, [%4];\n"
                 : "=r"(r0), "=r"(r1), "=r"(r2), "=r"(r3) : "r"(a));
}
__device__ __forceinline__ void mma_bf16(float* d,
                                         uint32_t a0, uint32_t a1, uint32_t a2, uint32_t a3,
                                         uint32_t b0, uint32_t b1) {
    asm volatile(
        "mma.sync.aligned.m16n8k16.row.col.f32.bf16.bf16.f32 "
        "{%0,%1,%2,%3}, {%4,%5,%6,%7}, {%8,%9}, {%0,%1,%2,%3};\n"
        : "+f"(d[0]), "+f"(d[1]), "+f"(d[2]), "+f"(d[3])
        : "r"(a0), "r"(a1), "r"(a2), "r"(a3), "r"(b0), "r"(b1));
}

// ---------------- stage loader: A(64xKC) hi/lo + B(128xKC) hi/lo ----------------
__device__ __forceinline__ void load_stage(
    const __nv_bfloat16* a_hi, const __nv_bfloat16* a_lo, size_t astr,
    const __nv_bfloat16* b_hi, const __nv_bfloat16* b_lo, size_t bstr,
    uint32_t st, int kc, uint64_t pol_a, uint64_t pol_b)
{
    const int tid = threadIdx.x;
    // A: 64 rows x 4 chunks of 16B (KC=32 -> 64B/row)
    {
        int i = tid;                       // 0..255 exactly covers 64*4
        int row = i >> 2, col8 = (i & 3) * 8;
        uint32_t dst = st + (uint32_t)(row * PADW + col8) * 2;
        size_t so = (size_t)row * astr + kc + col8;
        cp16p(dst,           a_hi + so, pol_a);
        cp16p(dst + A_BYTES, a_lo + so, pol_a);
    }
    // B: 128 rows x 4 chunks of 16B
#pragma unroll
    for (int i = tid; i < 128 * 4; i += 256) {
        int row = i >> 2, col8 = (i & 3) * 8;
        uint32_t dst = st + 2 * A_BYTES + (uint32_t)(row * PADW + col8) * 2;
        size_t so = (size_t)row * bstr + kc + col8;
        cp16p(dst,           b_hi + so, pol_b);
        cp16p(dst + B_BYTES, b_lo + so, pol_b);
    }
}

// ---------------- split-bf16 GEMM core: D(64x128) = A(64,K) @ B(128,K)^T ----------------
// 8 warps (2x4), warp tile 32x32, 3-stage cp.async ring (2 loads in flight).
__device__ __forceinline__ void gemm3_core(
    const __nv_bfloat16* a_hi, const __nv_bfloat16* a_lo, size_t astr,
    const __nv_bfloat16* b_hi, const __nv_bfloat16* b_lo, size_t bstr,
    char* sm, float d[2][4][4], int nchunks, uint64_t pol_a, uint64_t pol_b)
{
    const int lane = threadIdx.x & 31;
    const int warp = threadIdx.x >> 5;
    const int wm = warp >> 2;        // 0..1
    const int wn = warp & 3;         // 0..3

    const int qa = lane >> 3, ra = lane & 7;
    const int a_row0 = wm * 32 + (qa & 1) * 8 + ra;
    const int a_col0 = (qa >> 1) * 8;
    const int qb = lane >> 3, rb = lane & 7;
    const int b_row0 = wn * 32 + (qb >> 1) * 8 + rb;
    const int b_col0 = (qb & 1) * 8;

    const uint32_t smbase = smem_u32(sm);

    load_stage(a_hi, a_lo, astr, b_hi, b_lo, bstr, smbase, 0, pol_a, pol_b);
    cp_commit();
    load_stage(a_hi, a_lo, astr, b_hi, b_lo, bstr, smbase + STAGE_BYTES, KC, pol_a, pol_b);
    cp_commit();

#pragma unroll 1
    for (int c = 0; c < nchunks; c++) {
        // always keep 2 loads in flight (tail wraps: harmless redundant load)
        int nc = c + 2;
        if (nc >= nchunks) nc -= nchunks;
        load_stage(a_hi, a_lo, astr, b_hi, b_lo, bstr,
                   smbase + (uint32_t)((c + 2) % NSTAGE) * STAGE_BYTES, nc * KC,
                   pol_a, pol_b);
        cp_commit();
        cp_wait<2>();
        __syncthreads();

        const uint32_t sa = smbase + (uint32_t)(c % NSTAGE) * STAGE_BYTES;
        const uint32_t sb = sa + 2 * A_BYTES;
#pragma unroll
        for (int ks = 0; ks < KC / 16; ks++) {
            const int k0 = ks * 16;
            uint32_t ah[2][4], al[2][4], bh[2][4], bl[2][4];
#pragma unroll
            for (int mb = 0; mb < 2; mb++) {
                uint32_t aaddr = sa + (uint32_t)((a_row0 + mb * 16) * PADW + a_col0 + k0) * 2;
                ldm_x4(aaddr,           ah[mb][0], ah[mb][1], ah[mb][2], ah[mb][3]);
                ldm_x4(aaddr + A_BYTES, al[mb][0], al[mb][1], al[mb][2], al[mb][3]);
            }
#pragma unroll
            for (int np = 0; np < 2; np++) {
                uint32_t baddr = sb + (uint32_t)((b_row0 + np * 16) * PADW + b_col0 + k0) * 2;
                ldm_x4(baddr,           bh[np][0], bh[np][1], bh[np][2], bh[np][3]);
                ldm_x4(baddr + B_BYTES, bl[np][0], bl[np][1], bl[np][2], bl[np][3]);
            }
#pragma unroll
            for (int mb = 0; mb < 2; mb++)
#pragma unroll
                for (int nb = 0; nb < 4; nb++) {
                    const int np = nb >> 1, hf = (nb & 1) * 2;
                    float* acc = d[mb][nb];
                    mma_bf16(acc, ah[mb][0], ah[mb][1], ah[mb][2], ah[mb][3],
                             bh[np][hf], bh[np][hf + 1]);
                    mma_bf16(acc, al[mb][0], al[mb][1], al[mb][2], al[mb][3],
                             bh[np][hf], bh[np][hf + 1]);
                    mma_bf16(acc, ah[mb][0], ah[mb][1], ah[mb][2], ah[mb][3],
                             bl[np][hf], bl[np][hf + 1]);
                }
        }
        __syncthreads();
    }
}

// ---------------- prep ----------------
__global__ void split_whh_kernel(const float* __restrict__ w) {
    const size_t n = (size_t)NG * NG;
    for (size_t i = (size_t)blockIdx.x * blockDim.x + threadIdx.x; i < n;
         i += (size_t)gridDim.x * blockDim.x) {
        float x = w[i];
        __nv_bfloat16 h = __float2bfloat16(x);
        g_Whh_hi[i] = h;
        g_Whh_lo[i] = __float2bfloat16(x - __bfloat162float(h));
    }
}
__global__ void split_wdec_kernel(const float* __restrict__ w) {
    const size_t n = (size_t)NPL * NG;
    for (size_t i = (size_t)blockIdx.x * blockDim.x + threadIdx.x; i < n;
         i += (size_t)gridDim.x * blockDim.x) {
        float x = w[i];
        __nv_bfloat16 h = __float2bfloat16(x);
        g_Wdec_hi[i] = h;
        g_Wdec_lo[i] = __float2bfloat16(x - __bfloat162float(h));
    }
}

__global__ void h0_kernel(const float* __restrict__ p0, const float* __restrict__ Winit) {
    __shared__ float sP[64][33];
    __shared__ float sW[64][33];
    const int gbase = blockIdx.x * 64;
    const int tx = threadIdx.x & 15, ty = threadIdx.x >> 4;
    float acc[4][4] = {};
    for (int kc = 0; kc < 512; kc += 32) {
        for (int i = threadIdx.x; i < 64 * 32; i += 256) {
            int r = i >> 5, c = i & 31;
            sP[r][c] = p0[r * 512 + kc + c];
            sW[r][c] = Winit[(size_t)(gbase + r) * 512 + kc + c];
        }
        __syncthreads();
#pragma unroll
        for (int kk = 0; kk < 32; kk++) {
            float a[4], b[4];
#pragma unroll
            for (int i = 0; i < 4; i++) a[i] = sP[ty * 4 + i][kk];
#pragma unroll
            for (int j = 0; j < 4; j++) b[j] = sW[tx * 4 + j][kk];
#pragma unroll
            for (int i = 0; i < 4; i++)
#pragma unroll
                for (int j = 0; j < 4; j++) acc[i][j] = fmaf(a[i], b[j], acc[i][j]);
        }
        __syncthreads();
    }
#pragma unroll
    for (int i = 0; i < 4; i++) {
        int b = ty * 4 + i;
#pragma unroll
        for (int j = 0; j < 4; j++) {
            int g = gbase + tx * 4 + j;
            float h = acc[i][j];
            __nv_bfloat16 hh = __float2bfloat16(h);
            g_h0_hi[b * NG + g] = hh;
            g_h0_lo[b * NG + g] = __float2bfloat16(h - __bfloat162float(hh));
        }
    }
}

// ---------------- step: D[b][g] tile 64x128, K-split x8, fused epilogue ----------------
__global__ void __launch_bounds__(256, 2)
step_kernel(const float* __restrict__ v, const float* __restrict__ Wih, int t) {
    extern __shared__ char smd[];
    const int tid = threadIdx.x;
    const int n = blockIdx.x;       // g-slab (128 wide), 0..31
    const int kq = blockIdx.y;      // 0..7
    const size_t koff = (size_t)kq * KSEG;

    const uint64_t pl = pol_evict_last();

    const __nv_bfloat16* ahi = (t == 0 ? g_h0_hi : g_hs_hi + (size_t)(t - 1) * NG) + koff;
    const __nv_bfloat16* alo = (t == 0 ? g_h0_lo : g_hs_lo + (size_t)(t - 1) * NG) + koff;
    const size_t astr = (t == 0) ? (size_t)NG : (size_t)SS * NG;
    const __nv_bfloat16* bhi = g_Whh_hi + (size_t)n * 128 * NG + koff;
    const __nv_bfloat16* blo = g_Whh_lo + (size_t)n * 128 * NG + koff;

    float d[2][4][4] = {};
    gemm3_core(ahi, alo, astr, bhi, blo, NG, smd, d, STEP_CHUNKS, pl, pl);

    // write fp32 partial tile [b][g_local] (64x128)
    const int lane = tid & 31, warp = tid >> 5;
    const int wm = warp >> 2, wn = warp & 3;
    float* part = g_part + ((size_t)n * KSPLIT + kq) * (64 * 128);
#pragma unroll
    for (int mb = 0; mb < 2; mb++)
#pragma unroll
        for (int nb = 0; nb < 4; nb++) {
            int row = wm * 32 + mb * 16 + (lane >> 2);
            int col = wn * 32 + nb * 8 + (lane & 3) * 2;
            *(float2*)&part[row * 128 + col] = make_float2(d[mb][nb][0], d[mb][nb][1]);
            *(float2*)&part[(row + 8) * 128 + col] = make_float2(d[mb][nb][2], d[mb][nb][3]);
        }

    __shared__ int s_last;
    __syncthreads();
    if (tid == 0) {
        __threadfence();
        s_last = ((atomicAdd(&g_cnt[n], 1u) & 7u) == 7u) ? 1 : 0;
    }
    __syncthreads();
    if (!s_last) return;

    // fused epilogue: sum 8 partials + Wih*v + relu + hi/lo split
    const float* pb = g_part + (size_t)n * KSPLIT * (64 * 128);
    for (int i = tid; i < 64 * 128; i += 256) {
        int b = i >> 7, g = i & 127;
        float x = 0.f;
#pragma unroll
        for (int kk = 0; kk < KSPLIT; kk++) x += pb[kk * (64 * 128) + i];
        x += v[(b * SS + t) * 2 + 0] * Wih[(n * 128 + g) * 2 + 0]
           + v[(b * SS + t) * 2 + 1] * Wih[(n * 128 + g) * 2 + 1];
        x = fmaxf(x, 0.f);
        __nv_bfloat16 xh = __float2bfloat16(x);
        size_t o = ((size_t)b * SS + t) * NG + (size_t)n * 128 + g;
        g_hs_hi[o] = xh;
        g_hs_lo[o] = __float2bfloat16(x - __bfloat162float(xh));
    }
}

// ---------------- decoder: out = hs @ Wdec^T, tiles 64x128 ----------------
__global__ void __launch_bounds__(256, 2)
dec_kernel(float* __restrict__ out) {
    extern __shared__ char smd[];
    const int mbase = blockIdx.x * 64;     // rows over B*S (row = b*SS+t)
    const int pbase = blockIdx.y * 128;    // cols over NPL

    const uint64_t pf = pol_evict_first();
    const uint64_t pl = pol_evict_last();

    float d[2][4][4] = {};
    gemm3_core(g_hs_hi + (size_t)mbase * NG, g_hs_lo + (size_t)mbase * NG, NG,
               g_Wdec_hi + (size_t)pbase * NG, g_Wdec_lo + (size_t)pbase * NG, NG,
               smd, d, DEC_CHUNKS, pf, pl);

    const int lane = threadIdx.x & 31, warp = threadIdx.x >> 5;
    const int wm = warp >> 2, wn = warp & 3;
#pragma unroll
    for (int mb = 0; mb < 2; mb++)
#pragma unroll
        for (int nb = 0; nb < 4; nb++) {
            int row = mbase + wm * 32 + mb * 16 + (lane >> 2);
            int col = pbase + wn * 32 + nb * 8 + (lane & 3) * 2;
            *(float2*)&out[(size_t)row * NPL + col] = make_float2(d[mb][nb][0], d[mb][nb][1]);
            *(float2*)&out[(size_t)(row + 8) * NPL + col] = make_float2(d[mb][nb][2], d[mb][nb][3]);
        }
}

extern "C" void kernel_launch(void* const* d_in, const int* in_sizes, int n_in,
                              void* d_out, int out_size) {
    const float* v     = (const float*)d_in[0];
    const float* p0    = (const float*)d_in[1];
    const float* Winit = (const float*)d_in[2];
    const float* Wih   = (const float*)d_in[3];
    const float* Whh   = (const float*)d_in[4];
    const float* Wdec  = (const float*)d_in[5];
    float* out = (float*)d_out;

    cudaFuncSetAttribute(step_kernel, cudaFuncAttributeMaxDynamicSharedMemorySize, SMEM_BYTES);
    cudaFuncSetAttribute(dec_kernel,  cudaFuncAttributeMaxDynamicSharedMemorySize, SMEM_BYTES);

    split_whh_kernel<<<2048, 256>>>(Whh);
    split_wdec_kernel<<<512, 256>>>(Wdec);
    h0_kernel<<<64, 256>>>(p0, Winit);
    for (int t = 0; t < SS; t++)
        step_kernel<<<dim3(32, KSPLIT), 256, SMEM_BYTES>>>(v, Wih, t);
    dec_kernel<<<dim3(BB * SS / 64, NPL / 128), 256, SMEM_BYTES>>>(out);
}

// round 8
// speedup vs baseline: 1.2817x; 1.2817x over previous
#include <cuda_runtime.h>
#include <cuda_bf16.h>
#include <stdint.h>

#define NG 4096
#define NPL 512
#define BB 64
#define SS 128
#define KC 32

#define KSPLIT 8
#define KSEG (NG / KSPLIT)          // 512
#define STEP_CHUNKS (KSEG / KC)     // 16
#define DEC_CHUNKS (NG / KC)        // 128

#define PADW 40
#define A_BYTES (64 * PADW * 2)     // 5120
#define B_BYTES (128 * PADW * 2)    // 10240
#define STAGE_BYTES (2 * A_BYTES + 2 * B_BYTES)   // 30720
#define SMEM_BYTES (3 * STAGE_BYTES)              // 92160

__device__ __nv_bfloat16 g_Whh_hi[(size_t)NG * NG];
__device__ __nv_bfloat16 g_Whh_lo[(size_t)NG * NG];
__device__ __nv_bfloat16 g_Wdec_hi[(size_t)NPL * NG];
__device__ __nv_bfloat16 g_Wdec_lo[(size_t)NPL * NG];
__device__ __nv_bfloat16 g_h0_hi[BB * NG];
__device__ __nv_bfloat16 g_h0_lo[BB * NG];
// hs layout: [b][t][g]
__device__ __nv_bfloat16 g_hs_hi[(size_t)BB * SS * NG];
__device__ __nv_bfloat16 g_hs_lo[(size_t)BB * SS * NG];
__device__ float g_part2[(size_t)2 * 32 * KSPLIT * 64 * 128];  // [parity][n][kq][b][g]
__device__ unsigned int g_scnt[32];   // partial arrivals per slab
__device__ unsigned int g_pcnt[32];   // publication arrivals per slab

// ---------------- PTX helpers ----------------
__device__ __forceinline__ uint32_t smem_u32(const void* p) {
    return (uint32_t)__cvta_generic_to_shared(p);
}
__device__ __forceinline__ void cp16(uint32_t dst, const void* src) {
    asm volatile("cp.async.cg.shared.global [%0], [%1], 16;\n" :: "r"(dst), "l"(src));
}
__device__ __forceinline__ void cp_commit() {
    asm volatile("cp.async.commit_group;\n" ::: "memory");
}
template<int N>
__device__ __forceinline__ void cp_wait() {
    asm volatile("cp.async.wait_group %0;\n" :: "n"(N) : "memory");
}
__device__ __forceinline__ void ldm_x4(uint32_t a, uint32_t& r0, uint32_t& r1,
                                       uint32_t& r2, uint32_t& r3) {
    asm volatile("ldmatrix.sync.aligned.m8n8.x4.shared.b16 {%0,%1,%2,%3}, [%4];\n"
                 : "=r"(r0), "=r"(r1), "=r"(r2), "=r"(r3) : "r"(a));
}
__device__ __forceinline__ void mma_bf16(float* d,
                                         uint32_t a0, uint32_t a1, uint32_t a2, uint32_t a3,
                                         uint32_t b0, uint32_t b1) {
    asm volatile(
        "mma.sync.aligned.m16n8k16.row.col.f32.bf16.bf16.f32 "
        "{%0,%1,%2,%3}, {%4,%5,%6,%7}, {%8,%9}, {%0,%1,%2,%3};\n"
        : "+f"(d[0]), "+f"(d[1]), "+f"(d[2]), "+f"(d[3])
        : "r"(a0), "r"(a1), "r"(a2), "r"(a3), "r"(b0), "r"(b1));
}
__device__ __forceinline__ unsigned int ld_acq(const unsigned int* p) {
    unsigned int x;
    asm volatile("ld.acquire.gpu.b32 %0, [%1];" : "=r"(x) : "l"(p) : "memory");
    return x;
}
__device__ __forceinline__ void poll_ge(const unsigned int* p, unsigned int target) {
    while (ld_acq(p) < target) __nanosleep(64);
}

// ---------------- stage loader: W first (unguarded), then A (guarded) ----------------
__device__ __forceinline__ void load_stage(
    const __nv_bfloat16* ahi, const __nv_bfloat16* alo, size_t astr,
    const __nv_bfloat16* bhi, const __nv_bfloat16* blo, size_t bstr,
    uint32_t st, int kc, unsigned int nd, const unsigned int* pc)
{
    const int tid = threadIdx.x;
#pragma unroll
    for (int i = tid; i < 128 * 4; i += 256) {
        int row = i >> 2, col8 = (i & 3) * 8;
        uint32_t dst = st + 2 * A_BYTES + (uint32_t)(row * PADW + col8) * 2;
        size_t so = (size_t)row * bstr + kc + col8;
        cp16(dst,           bhi + so);
        cp16(dst + B_BYTES, blo + so);
    }
    if (nd) poll_ge(pc, nd);
    {
        int i = tid;
        int row = i >> 2, col8 = (i & 3) * 8;
        uint32_t dst = st + (uint32_t)(row * PADW + col8) * 2;
        size_t so = (size_t)row * astr + kc + col8;
        cp16(dst,           ahi + so);
        cp16(dst + A_BYTES, alo + so);
    }
}

// ---------------- one 32-K chunk of 3-term MMAs ----------------
__device__ __forceinline__ void compute_chunk(
    uint32_t sa, int a_row0, int a_col0, int b_row0, int b_col0, float d[2][4][4])
{
    const uint32_t sb = sa + 2 * A_BYTES;
#pragma unroll
    for (int ks = 0; ks < KC / 16; ks++) {
        const int k0 = ks * 16;
        uint32_t ah[2][4], al[2][4], bh[2][4], bl[2][4];
#pragma unroll
        for (int mb = 0; mb < 2; mb++) {
            uint32_t aaddr = sa + (uint32_t)((a_row0 + mb * 16) * PADW + a_col0 + k0) * 2;
            ldm_x4(aaddr,           ah[mb][0], ah[mb][1], ah[mb][2], ah[mb][3]);
            ldm_x4(aaddr + A_BYTES, al[mb][0], al[mb][1], al[mb][2], al[mb][3]);
        }
#pragma unroll
        for (int np = 0; np < 2; np++) {
            uint32_t baddr = sb + (uint32_t)((b_row0 + np * 16) * PADW + b_col0 + k0) * 2;
            ldm_x4(baddr,           bh[np][0], bh[np][1], bh[np][2], bh[np][3]);
            ldm_x4(baddr + B_BYTES, bl[np][0], bl[np][1], bl[np][2], bl[np][3]);
        }
#pragma unroll
        for (int mb = 0; mb < 2; mb++)
#pragma unroll
            for (int nb = 0; nb < 4; nb++) {
                const int np = nb >> 1, hf = (nb & 1) * 2;
                float* acc = d[mb][nb];
                mma_bf16(acc, ah[mb][0], ah[mb][1], ah[mb][2], ah[mb][3],
                         bh[np][hf], bh[np][hf + 1]);
                mma_bf16(acc, al[mb][0], al[mb][1], al[mb][2], al[mb][3],
                         bh[np][hf], bh[np][hf + 1]);
                mma_bf16(acc, ah[mb][0], ah[mb][1], ah[mb][2], ah[mb][3],
                         bl[np][hf], bl[np][hf + 1]);
            }
    }
}

// ---------------- prep ----------------
__global__ void split_whh_kernel(const float* __restrict__ w) {
    const size_t n = (size_t)NG * NG;
    for (size_t i = (size_t)blockIdx.x * blockDim.x + threadIdx.x; i < n;
         i += (size_t)gridDim.x * blockDim.x) {
        float x = w[i];
        __nv_bfloat16 h = __float2bfloat16(x);
        g_Whh_hi[i] = h;
        g_Whh_lo[i] = __float2bfloat16(x - __bfloat162float(h));
    }
}
__global__ void split_wdec_kernel(const float* __restrict__ w) {
    const size_t n = (size_t)NPL * NG;
    for (size_t i = (size_t)blockIdx.x * blockDim.x + threadIdx.x; i < n;
         i += (size_t)gridDim.x * blockDim.x) {
        float x = w[i];
        __nv_bfloat16 h = __float2bfloat16(x);
        g_Wdec_hi[i] = h;
        g_Wdec_lo[i] = __float2bfloat16(x - __bfloat162float(h));
    }
}
__global__ void reset_kernel() {
    if (threadIdx.x < 32) {
        g_scnt[threadIdx.x] = 0u;
        g_pcnt[threadIdx.x] = 0u;
    }
}

__global__ void h0_kernel(const float* __restrict__ p0, const float* __restrict__ Winit) {
    __shared__ float sP[64][33];
    __shared__ float sW[64][33];
    const int gbase = blockIdx.x * 64;
    const int tx = threadIdx.x & 15, ty = threadIdx.x >> 4;
    float acc[4][4] = {};
    for (int kc = 0; kc < 512; kc += 32) {
        for (int i = threadIdx.x; i < 64 * 32; i += 256) {
            int r = i >> 5, c = i & 31;
            sP[r][c] = p0[r * 512 + kc + c];
            sW[r][c] = Winit[(size_t)(gbase + r) * 512 + kc + c];
        }
        __syncthreads();
#pragma unroll
        for (int kk = 0; kk < 32; kk++) {
            float a[4], b[4];
#pragma unroll
            for (int i = 0; i < 4; i++) a[i] = sP[ty * 4 + i][kk];
#pragma unroll
            for (int j = 0; j < 4; j++) b[j] = sW[tx * 4 + j][kk];
#pragma unroll
            for (int i = 0; i < 4; i++)
#pragma unroll
                for (int j = 0; j < 4; j++) acc[i][j] = fmaf(a[i], b[j], acc[i][j]);
        }
        __syncthreads();
    }
#pragma unroll
    for (int i = 0; i < 4; i++) {
        int b = ty * 4 + i;
#pragma unroll
        for (int j = 0; j < 4; j++) {
            int g = gbase + tx * 4 + j;
            float h = acc[i][j];
            __nv_bfloat16 hh = __float2bfloat16(h);
            g_h0_hi[b * NG + g] = hh;
            g_h0_lo[b * NG + g] = __float2bfloat16(h - __bfloat162float(hh));
        }
    }
}

// ---------------- persistent RNN kernel: all 128 steps ----------------
__global__ void __launch_bounds__(256, 2)
rnn_persistent(const float* __restrict__ v, const float* __restrict__ Wih) {
    extern __shared__ char smd[];
    const int tid = threadIdx.x;
    const int n  = blockIdx.x >> 3;     // 0..31
    const int kq = blockIdx.x & 7;      // 0..7
    const size_t koff = (size_t)kq * KSEG;

    const __nv_bfloat16* bhi = g_Whh_hi + (size_t)n * 128 * NG + koff;
    const __nv_bfloat16* blo = g_Whh_lo + (size_t)n * 128 * NG + koff;

    const int lane = tid & 31, warp = tid >> 5;
    const int wm = warp >> 2, wn = warp & 3;
    const int qa = lane >> 3, ra = lane & 7;
    const int a_row0 = wm * 32 + (qa & 1) * 8 + ra;
    const int a_col0 = (qa >> 1) * 8;
    const int qb = lane >> 3, rb = lane & 7;
    const int b_row0 = wn * 32 + (qb >> 1) * 8 + rb;
    const int b_col0 = (qb & 1) * 8;
    const uint32_t smbase = smem_u32(smd);

    // hoisted epilogue constants: this thread reduces b-row (kq*8 + warp), g-quad (lane*4)
    const int eb = kq * 8 + warp;        // 0..63
    const int eg = lane * 4;             // 0..124
    const int ggl = n * 128 + eg;
    float wih0[4], wih1[4];
#pragma unroll
    for (int j = 0; j < 4; j++) {
        wih0[j] = Wih[(ggl + j) * 2 + 0];
        wih1[j] = Wih[(ggl + j) * 2 + 1];
    }

#pragma unroll 1
    for (int t = 0; t < SS; t++) {
        const __nv_bfloat16* ahi = (t == 0 ? g_h0_hi : g_hs_hi + (size_t)(t - 1) * NG) + koff;
        const __nv_bfloat16* alo = (t == 0 ? g_h0_lo : g_hs_lo + (size_t)(t - 1) * NG) + koff;
        const size_t astr = (t == 0) ? (size_t)NG : (size_t)SS * NG;
        const unsigned int need = (t > 0) ? 8u * (unsigned)t : 0u;

        // prologue: 2 chunks in flight
        load_stage(ahi, alo, astr, bhi, blo, NG, smbase, 0, need, &g_pcnt[kq * 4]);
        cp_commit();
        load_stage(ahi, alo, astr, bhi, blo, NG, smbase + STAGE_BYTES, KC, 0u, 0);
        cp_commit();

        float d[2][4][4] = {};
#pragma unroll 1
        for (int c = 0; c < STEP_CHUNKS; c++) {
            if (c + 2 < STEP_CHUNKS) {
                const int kc = (c + 2) * KC;
                const unsigned int nd = (need && ((kc & 127) == 0)) ? need : 0u;
                load_stage(ahi, alo, astr, bhi, blo, NG,
                           smbase + (uint32_t)((c + 2) % 3) * STAGE_BYTES, kc,
                           nd, &g_pcnt[kq * 4 + (kc >> 7)]);
            }
            cp_commit();
            cp_wait<2>();
            __syncthreads();
            compute_chunk(smbase + (uint32_t)(c % 3) * STAGE_BYTES,
                          a_row0, a_col0, b_row0, b_col0, d);
            __syncthreads();
        }

        // write fp32 partial tile [b][g_local] (64x128), parity-buffered
        float* part = g_part2 + ((((size_t)(t & 1)) * 32 + n) * KSPLIT + kq) * (64 * 128);
#pragma unroll
        for (int mb = 0; mb < 2; mb++)
#pragma unroll
            for (int nb = 0; nb < 4; nb++) {
                int row = wm * 32 + mb * 16 + (lane >> 2);
                int col = wn * 32 + nb * 8 + (lane & 3) * 2;
                *(float2*)&part[row * 128 + col] = make_float2(d[mb][nb][0], d[mb][nb][1]);
                *(float2*)&part[(row + 8) * 128 + col] = make_float2(d[mb][nb][2], d[mb][nb][3]);
            }

        __threadfence();
        __syncthreads();
        if (tid == 0) atomicAdd(&g_scnt[n], 1u);
        poll_ge(&g_scnt[n], 8u * (unsigned)(t + 1));

        // distributed deterministic reduction: this CTA reduces b-rows [kq*8, kq*8+8)
        const float* pb = g_part2 + ((((size_t)(t & 1)) * 32 + n) * KSPLIT) * (64 * 128);
        float s0 = 0.f, s1 = 0.f, s2 = 0.f, s3 = 0.f;
#pragma unroll
        for (int j = 0; j < KSPLIT; j++) {
            float4 e = __ldcg((const float4*)(pb + (size_t)j * (64 * 128) + eb * 128 + eg));
            s0 += e.x; s1 += e.y; s2 += e.z; s3 += e.w;
        }
        const float v0 = v[(eb * SS + t) * 2 + 0];
        const float v1 = v[(eb * SS + t) * 2 + 1];
        float x0 = fmaxf(s0 + v0 * wih0[0] + v1 * wih1[0], 0.f);
        float x1 = fmaxf(s1 + v0 * wih0[1] + v1 * wih1[1], 0.f);
        float x2 = fmaxf(s2 + v0 * wih0[2] + v1 * wih1[2], 0.f);
        float x3 = fmaxf(s3 + v0 * wih0[3] + v1 * wih1[3], 0.f);
        __nv_bfloat16 h0b = __float2bfloat16(x0), h1b = __float2bfloat16(x1);
        __nv_bfloat16 h2b = __float2bfloat16(x2), h3b = __float2bfloat16(x3);
        __nv_bfloat162 hi01 = __halves2bfloat162(h0b, h1b);
        __nv_bfloat162 hi23 = __halves2bfloat162(h2b, h3b);
        __nv_bfloat162 lo01 = __halves2bfloat162(
            __float2bfloat16(x0 - __bfloat162float(h0b)),
            __float2bfloat16(x1 - __bfloat162float(h1b)));
        __nv_bfloat162 lo23 = __halves2bfloat162(
            __float2bfloat16(x2 - __bfloat162float(h2b)),
            __float2bfloat16(x3 - __bfloat162float(h3b)));
        size_t o = ((size_t)eb * SS + t) * NG + ggl;
        *(uint2*)&g_hs_hi[o] = make_uint2(*(uint32_t*)&hi01, *(uint32_t*)&hi23);
        *(uint2*)&g_hs_lo[o] = make_uint2(*(uint32_t*)&lo01, *(uint32_t*)&lo23);

        __threadfence();
        __syncthreads();
        if (tid == 0) atomicAdd(&g_pcnt[n], 1u);
    }
}

// ---------------- decoder: out = hs @ Wdec^T, tiles 64x128 ----------------
__global__ void __launch_bounds__(256, 2)
dec_kernel(float* __restrict__ out) {
    extern __shared__ char smd[];
    const int tid = threadIdx.x;
    const int mbase = blockIdx.x * 64;
    const int pbase = blockIdx.y * 128;

    const __nv_bfloat16* ahi = g_hs_hi + (size_t)mbase * NG;
    const __nv_bfloat16* alo = g_hs_lo + (size_t)mbase * NG;
    const __nv_bfloat16* bhi = g_Wdec_hi + (size_t)pbase * NG;
    const __nv_bfloat16* blo = g_Wdec_lo + (size_t)pbase * NG;

    const int lane = tid & 31, warp = tid >> 5;
    const int wm = warp >> 2, wn = warp & 3;
    const int qa = lane >> 3, ra = lane & 7;
    const int a_row0 = wm * 32 + (qa & 1) * 8 + ra;
    const int a_col0 = (qa >> 1) * 8;
    const int qb = lane >> 3, rb = lane & 7;
    const int b_row0 = wn * 32 + (qb >> 1) * 8 + rb;
    const int b_col0 = (qb & 1) * 8;
    const uint32_t smbase = smem_u32(smd);

    load_stage(ahi, alo, NG, bhi, blo, NG, smbase, 0, 0u, 0);
    cp_commit();
    load_stage(ahi, alo, NG, bhi, blo, NG, smbase + STAGE_BYTES, KC, 0u, 0);
    cp_commit();

    float d[2][4][4] = {};
#pragma unroll 1
    for (int c = 0; c < DEC_CHUNKS; c++) {
        if (c + 2 < DEC_CHUNKS)
            load_stage(ahi, alo, NG, bhi, blo, NG,
                       smbase + (uint32_t)((c + 2) % 3) * STAGE_BYTES, (c + 2) * KC, 0u, 0);
        cp_commit();
        cp_wait<2>();
        __syncthreads();
        compute_chunk(smbase + (uint32_t)(c % 3) * STAGE_BYTES,
                      a_row0, a_col0, b_row0, b_col0, d);
        __syncthreads();
    }

#pragma unroll
    for (int mb = 0; mb < 2; mb++)
#pragma unroll
        for (int nb = 0; nb < 4; nb++) {
            int row = mbase + wm * 32 + mb * 16 + (lane >> 2);
            int col = pbase + wn * 32 + nb * 8 + (lane & 3) * 2;
            *(float2*)&out[(size_t)row * NPL + col] = make_float2(d[mb][nb][0], d[mb][nb][1]);
            *(float2*)&out[(size_t)(row + 8) * NPL + col] = make_float2(d[mb][nb][2], d[mb][nb][3]);
        }
}

extern "C" void kernel_launch(void* const* d_in, const int* in_sizes, int n_in,
                              void* d_out, int out_size) {
    const float* v     = (const float*)d_in[0];
    const float* p0    = (const float*)d_in[1];
    const float* Winit = (const float*)d_in[2];
    const float* Wih   = (const float*)d_in[3];
    const float* Whh   = (const float*)d_in[4];
    const float* Wdec  = (const float*)d_in[5];
    float* out = (float*)d_out;

    cudaFuncSetAttribute(rnn_persistent, cudaFuncAttributeMaxDynamicSharedMemorySize, SMEM_BYTES);
    cudaFuncSetAttribute(dec_kernel,     cudaFuncAttributeMaxDynamicSharedMemorySize, SMEM_BYTES);

    split_whh_kernel<<<2048, 256>>>(Whh);
    split_wdec_kernel<<<512, 256>>>(Wdec);
    h0_kernel<<<64, 256>>>(p0, Winit);
    reset_kernel<<<1, 32>>>();
    rnn_persistent<<<256, 256, SMEM_BYTES>>>(v, Wih);
    dec_kernel<<<dim3(BB * SS / 64, NPL / 128), 256, SMEM_BYTES>>>(out);
}

// round 9
// speedup vs baseline: 1.4437x; 1.1263x over previous
#include <cuda_runtime.h>
#include <cuda_bf16.h>
#include <stdint.h>

#define NG 4096
#define NPL 512
#define BB 64
#define SS 128
#define KC 32

#define KSPLIT 8
#define KSEG (NG / KSPLIT)          // 512
#define STEP_CHUNKS (KSEG / KC)     // 16
#define DEC_CHUNKS (NG / KC)        // 128

#define PADW 40
#define A_BYTES (64 * PADW * 2)     // 5120
#define B_BYTES (128 * PADW * 2)    // 10240
#define STAGE_BYTES (2 * A_BYTES + 2 * B_BYTES)   // 30720
#define SMEM_BYTES (3 * STAGE_BYTES)              // 92160

__device__ __nv_bfloat16 g_Whh_hi[(size_t)NG * NG];
__device__ __nv_bfloat16 g_Whh_lo[(size_t)NG * NG];
__device__ __nv_bfloat16 g_Wdec_hi[(size_t)NPL * NG];
__device__ __nv_bfloat16 g_Wdec_lo[(size_t)NPL * NG];
__device__ __nv_bfloat16 g_h0_hi[BB * NG];
__device__ __nv_bfloat16 g_h0_lo[BB * NG];
// hs layout: [b][t][g]
__device__ __nv_bfloat16 g_hs_hi[(size_t)BB * SS * NG];
__device__ __nv_bfloat16 g_hs_lo[(size_t)BB * SS * NG];
__device__ float g_part2[(size_t)2 * 32 * KSPLIT * 64 * 128];  // [parity][n][kq][b][g]
__device__ unsigned int g_scnt[32];
__device__ unsigned int g_pcnt[32];

// ---------------- PTX helpers ----------------
__device__ __forceinline__ uint32_t smem_u32(const void* p) {
    return (uint32_t)__cvta_generic_to_shared(p);
}
__device__ __forceinline__ void cp16(uint32_t dst, const void* src) {
    asm volatile("cp.async.cg.shared.global [%0], [%1], 16;\n" :: "r"(dst), "l"(src));
}
__device__ __forceinline__ void cp_commit() {
    asm volatile("cp.async.commit_group;\n" ::: "memory");
}
template<int N>
__device__ __forceinline__ void cp_wait() {
    asm volatile("cp.async.wait_group %0;\n" :: "n"(N) : "memory");
}
__device__ __forceinline__ void ldm_x4(uint32_t a, uint32_t& r0, uint32_t& r1,
                                       uint32_t& r2, uint32_t& r3) {
    asm volatile("ldmatrix.sync.aligned.m8n8.x4.shared.b16 {%0,%1,%2,%3}, [%4];\n"
                 : "=r"(r0), "=r"(r1), "=r"(r2), "=r"(r3) : "r"(a));
}
__device__ __forceinline__ void mma_bf16(float* d,
                                         uint32_t a0, uint32_t a1, uint32_t a2, uint32_t a3,
                                         uint32_t b0, uint32_t b1) {
    asm volatile(
        "mma.sync.aligned.m16n8k16.row.col.f32.bf16.bf16.f32 "
        "{%0,%1,%2,%3}, {%4,%5,%6,%7}, {%8,%9}, {%0,%1,%2,%3};\n"
        : "+f"(d[0]), "+f"(d[1]), "+f"(d[2]), "+f"(d[3])
        : "r"(a0), "r"(a1), "r"(a2), "r"(a3), "r"(b0), "r"(b1));
}
__device__ __forceinline__ unsigned int ld_acq(const unsigned int* p) {
    unsigned int x;
    asm volatile("ld.acquire.gpu.b32 %0, [%1];" : "=r"(x) : "l"(p) : "memory");
    return x;
}
__device__ __forceinline__ void poll_ge(const unsigned int* p, unsigned int target) {
    while (ld_acq(p) < target) __nanosleep(64);
}

// ---------------- split loaders ----------------
__device__ __forceinline__ void load_W(
    const __nv_bfloat16* bhi, const __nv_bfloat16* blo, size_t bstr,
    uint32_t st, int kc)
{
    const int tid = threadIdx.x;
#pragma unroll
    for (int i = tid; i < 128 * 4; i += 256) {
        int row = i >> 2, col8 = (i & 3) * 8;
        uint32_t dst = st + 2 * A_BYTES + (uint32_t)(row * PADW + col8) * 2;
        size_t so = (size_t)row * bstr + kc + col8;
        cp16(dst,           bhi + so);
        cp16(dst + B_BYTES, blo + so);
    }
}
__device__ __forceinline__ void load_A(
    const __nv_bfloat16* ahi, const __nv_bfloat16* alo, size_t astr,
    uint32_t st, int kc)
{
    const int i = threadIdx.x;           // 256 threads cover 64 rows x 4 x 16B
    int row = i >> 2, col8 = (i & 3) * 8;
    uint32_t dst = st + (uint32_t)(row * PADW + col8) * 2;
    size_t so = (size_t)row * astr + kc + col8;
    cp16(dst,           ahi + so);
    cp16(dst + A_BYTES, alo + so);
}

// ---------------- one 32-K chunk of 3-term MMAs ----------------
__device__ __forceinline__ void compute_chunk(
    uint32_t sa, int a_row0, int a_col0, int b_row0, int b_col0, float d[2][4][4])
{
    const uint32_t sb = sa + 2 * A_BYTES;
#pragma unroll
    for (int ks = 0; ks < KC / 16; ks++) {
        const int k0 = ks * 16;
        uint32_t ah[2][4], al[2][4], bh[2][4], bl[2][4];
#pragma unroll
        for (int mb = 0; mb < 2; mb++) {
            uint32_t aaddr = sa + (uint32_t)((a_row0 + mb * 16) * PADW + a_col0 + k0) * 2;
            ldm_x4(aaddr,           ah[mb][0], ah[mb][1], ah[mb][2], ah[mb][3]);
            ldm_x4(aaddr + A_BYTES, al[mb][0], al[mb][1], al[mb][2], al[mb][3]);
        }
#pragma unroll
        for (int np = 0; np < 2; np++) {
            uint32_t baddr = sb + (uint32_t)((b_row0 + np * 16) * PADW + b_col0 + k0) * 2;
            ldm_x4(baddr,           bh[np][0], bh[np][1], bh[np][2], bh[np][3]);
            ldm_x4(baddr + B_BYTES, bl[np][0], bl[np][1], bl[np][2], bl[np][3]);
        }
#pragma unroll
        for (int mb = 0; mb < 2; mb++)
#pragma unroll
            for (int nb = 0; nb < 4; nb++) {
                const int np = nb >> 1, hf = (nb & 1) * 2;
                float* acc = d[mb][nb];
                mma_bf16(acc, ah[mb][0], ah[mb][1], ah[mb][2], ah[mb][3],
                         bh[np][hf], bh[np][hf + 1]);
                mma_bf16(acc, al[mb][0], al[mb][1], al[mb][2], al[mb][3],
                         bh[np][hf], bh[np][hf + 1]);
                mma_bf16(acc, ah[mb][0], ah[mb][1], ah[mb][2], ah[mb][3],
                         bl[np][hf], bl[np][hf + 1]);
            }
    }
}

// ---------------- prep ----------------
__global__ void split_whh_kernel(const float* __restrict__ w) {
    const size_t n = (size_t)NG * NG;
    for (size_t i = (size_t)blockIdx.x * blockDim.x + threadIdx.x; i < n;
         i += (size_t)gridDim.x * blockDim.x) {
        float x = w[i];
        __nv_bfloat16 h = __float2bfloat16(x);
        g_Whh_hi[i] = h;
        g_Whh_lo[i] = __float2bfloat16(x - __bfloat162float(h));
    }
}
__global__ void split_wdec_kernel(const float* __restrict__ w) {
    const size_t n = (size_t)NPL * NG;
    for (size_t i = (size_t)blockIdx.x * blockDim.x + threadIdx.x; i < n;
         i += (size_t)gridDim.x * blockDim.x) {
        float x = w[i];
        __nv_bfloat16 h = __float2bfloat16(x);
        g_Wdec_hi[i] = h;
        g_Wdec_lo[i] = __float2bfloat16(x - __bfloat162float(h));
    }
}
__global__ void reset_kernel() {
    if (threadIdx.x < 32) {
        g_scnt[threadIdx.x] = 0u;
        g_pcnt[threadIdx.x] = 0u;
    }
}

__global__ void h0_kernel(const float* __restrict__ p0, const float* __restrict__ Winit) {
    __shared__ float sP[64][33];
    __shared__ float sW[64][33];
    const int gbase = blockIdx.x * 64;
    const int tx = threadIdx.x & 15, ty = threadIdx.x >> 4;
    float acc[4][4] = {};
    for (int kc = 0; kc < 512; kc += 32) {
        for (int i = threadIdx.x; i < 64 * 32; i += 256) {
            int r = i >> 5, c = i & 31;
            sP[r][c] = p0[r * 512 + kc + c];
            sW[r][c] = Winit[(size_t)(gbase + r) * 512 + kc + c];
        }
        __syncthreads();
#pragma unroll
        for (int kk = 0; kk < 32; kk++) {
            float a[4], b[4];
#pragma unroll
            for (int i = 0; i < 4; i++) a[i] = sP[ty * 4 + i][kk];
#pragma unroll
            for (int j = 0; j < 4; j++) b[j] = sW[tx * 4 + j][kk];
#pragma unroll
            for (int i = 0; i < 4; i++)
#pragma unroll
                for (int j = 0; j < 4; j++) acc[i][j] = fmaf(a[i], b[j], acc[i][j]);
        }
        __syncthreads();
    }
#pragma unroll
    for (int i = 0; i < 4; i++) {
        int b = ty * 4 + i;
#pragma unroll
        for (int j = 0; j < 4; j++) {
            int g = gbase + tx * 4 + j;
            float h = acc[i][j];
            __nv_bfloat16 hh = __float2bfloat16(h);
            g_h0_hi[b * NG + g] = hh;
            g_h0_lo[b * NG + g] = __float2bfloat16(h - __bfloat162float(hh));
        }
    }
}

// ---------------- persistent RNN kernel: all 128 steps ----------------
__global__ void __launch_bounds__(256, 2)
rnn_persistent(const float* __restrict__ v, const float* __restrict__ Wih) {
    extern __shared__ char smd[];
    const int tid = threadIdx.x;
    const int n  = blockIdx.x >> 3;     // 0..31
    const int kq = blockIdx.x & 7;      // 0..7
    const size_t koff = (size_t)kq * KSEG;

    const __nv_bfloat16* bhi = g_Whh_hi + (size_t)n * 128 * NG + koff;
    const __nv_bfloat16* blo = g_Whh_lo + (size_t)n * 128 * NG + koff;

    const int lane = tid & 31, warp = tid >> 5;
    const int wm = warp >> 2, wn = warp & 3;
    const int qa = lane >> 3, ra = lane & 7;
    const int a_row0 = wm * 32 + (qa & 1) * 8 + ra;
    const int a_col0 = (qa >> 1) * 8;
    const int qb = lane >> 3, rb = lane & 7;
    const int b_row0 = wn * 32 + (qb >> 1) * 8 + rb;
    const int b_col0 = (qb & 1) * 8;
    const uint32_t smbase = smem_u32(smd);

    // epilogue constants: this thread reduces b-row (kq*8 + warp), g-quad (lane*4)
    const int eb = kq * 8 + warp;
    const int eg = lane * 4;
    const int ggl = n * 128 + eg;
    float wih0[4], wih1[4];
#pragma unroll
    for (int j = 0; j < 4; j++) {
        wih0[j] = Wih[(ggl + j) * 2 + 0];
        wih1[j] = Wih[(ggl + j) * 2 + 1];
    }

    // t=0 prologue: W + A (h0, unguarded) for chunks 0,1
    {
        const __nv_bfloat16* ahi = g_h0_hi + koff;
        const __nv_bfloat16* alo = g_h0_lo + koff;
        load_W(bhi, blo, NG, smbase + 0 * STAGE_BYTES, 0);
        load_W(bhi, blo, NG, smbase + 1 * STAGE_BYTES, KC);
        cp_commit();
        load_A(ahi, alo, NG, smbase + 0 * STAGE_BYTES, 0);
        cp_commit();
        load_A(ahi, alo, NG, smbase + 1 * STAGE_BYTES, KC);
        cp_commit();
    }

#pragma unroll 1
    for (int t = 0; t < SS; t++) {
        const __nv_bfloat16* ahi = (t == 0 ? g_h0_hi : g_hs_hi + (size_t)(t - 1) * NG) + koff;
        const __nv_bfloat16* alo = (t == 0 ? g_h0_lo : g_hs_lo + (size_t)(t - 1) * NG) + koff;
        const size_t astr = (t == 0) ? (size_t)NG : (size_t)SS * NG;
        const unsigned int need = 8u * (unsigned)t;   // A-guard for step t (0 for t=0)
        const int cg0 = t * STEP_CHUNKS;              // global chunk base

        float d[2][4][4] = {};
#pragma unroll 1
        for (int c = 0; c < STEP_CHUNKS; c++) {
            if (c == 1) cp_wait<0>(); else cp_wait<1>();
            __syncthreads();
            const uint32_t sa = smbase + (uint32_t)((cg0 + c) % 3) * STAGE_BYTES;
            compute_chunk(sa, a_row0, a_col0, b_row0, b_col0, d);

            // issue load for chunk c+2
            const int cn = c + 2;
            const uint32_t stn = smbase + (uint32_t)((cg0 + cn) % 3) * STAGE_BYTES;
            if (cn < STEP_CHUNKS) {
                const int kc = cn * KC;
                load_W(bhi, blo, NG, stn, kc);
                if (need && ((kc & 127) == 0))
                    poll_ge(&g_pcnt[kq * 4 + (kc >> 7)], need);
                load_A(ahi, alo, astr, stn, kc);
            } else if (t + 1 < SS) {
                // W-only prefetch for next step's chunk (cn-16)
                load_W(bhi, blo, NG, stn, (cn - STEP_CHUNKS) * KC);
            }
            cp_commit();
        }

        // write fp32 partial tile [b][g_local] (64x128), parity-buffered
        float* part = g_part2 + ((((size_t)(t & 1)) * 32 + n) * KSPLIT + kq) * (64 * 128);
#pragma unroll
        for (int mb = 0; mb < 2; mb++)
#pragma unroll
            for (int nb = 0; nb < 4; nb++) {
                int row = wm * 32 + mb * 16 + (lane >> 2);
                int col = wn * 32 + nb * 8 + (lane & 3) * 2;
                *(float2*)&part[row * 128 + col] = make_float2(d[mb][nb][0], d[mb][nb][1]);
                *(float2*)&part[(row + 8) * 128 + col] = make_float2(d[mb][nb][2], d[mb][nb][3]);
            }

        __threadfence();
        __syncthreads();
        if (tid == 0) atomicAdd(&g_scnt[n], 1u);
        poll_ge(&g_scnt[n], 8u * (unsigned)(t + 1));

        // distributed deterministic reduction (this CTA: b-rows [kq*8, kq*8+8))
        const float* pb = g_part2 + ((((size_t)(t & 1)) * 32 + n) * KSPLIT) * (64 * 128);
        float s0 = 0.f, s1 = 0.f, s2 = 0.f, s3 = 0.f;
#pragma unroll
        for (int j = 0; j < KSPLIT; j++) {
            float4 e = __ldcg((const float4*)(pb + (size_t)j * (64 * 128) + eb * 128 + eg));
            s0 += e.x; s1 += e.y; s2 += e.z; s3 += e.w;
        }
        const float v0 = v[(eb * SS + t) * 2 + 0];
        const float v1 = v[(eb * SS + t) * 2 + 1];
        float x0 = fmaxf(s0 + v0 * wih0[0] + v1 * wih1[0], 0.f);
        float x1 = fmaxf(s1 + v0 * wih0[1] + v1 * wih1[1], 0.f);
        float x2 = fmaxf(s2 + v0 * wih0[2] + v1 * wih1[2], 0.f);
        float x3 = fmaxf(s3 + v0 * wih0[3] + v1 * wih1[3], 0.f);
        __nv_bfloat16 h0b = __float2bfloat16(x0), h1b = __float2bfloat16(x1);
        __nv_bfloat16 h2b = __float2bfloat16(x2), h3b = __float2bfloat16(x3);
        __nv_bfloat162 hi01 = __halves2bfloat162(h0b, h1b);
        __nv_bfloat162 hi23 = __halves2bfloat162(h2b, h3b);
        __nv_bfloat162 lo01 = __halves2bfloat162(
            __float2bfloat16(x0 - __bfloat162float(h0b)),
            __float2bfloat16(x1 - __bfloat162float(h1b)));
        __nv_bfloat162 lo23 = __halves2bfloat162(
            __float2bfloat16(x2 - __bfloat162float(h2b)),
            __float2bfloat16(x3 - __bfloat162float(h3b)));
        size_t o = ((size_t)eb * SS + t) * NG + ggl;
        *(uint2*)&g_hs_hi[o] = make_uint2(*(uint32_t*)&hi01, *(uint32_t*)&hi23);
        *(uint2*)&g_hs_lo[o] = make_uint2(*(uint32_t*)&lo01, *(uint32_t*)&lo23);

        __threadfence();
        __syncthreads();
        if (tid == 0) atomicAdd(&g_pcnt[n], 1u);

        // A loads for next step's chunks 0,1 (W already prefetched in-loop)
        if (t + 1 < SS) {
            const __nv_bfloat16* nahi = g_hs_hi + (size_t)t * NG + koff;
            const __nv_bfloat16* nalo = g_hs_lo + (size_t)t * NG + koff;
            const int ncg = (t + 1) * STEP_CHUNKS;
            poll_ge(&g_pcnt[kq * 4], 8u * (unsigned)(t + 1));
            load_A(nahi, nalo, (size_t)SS * NG, smbase + (uint32_t)(ncg % 3) * STAGE_BYTES, 0);
            cp_commit();
            load_A(nahi, nalo, (size_t)SS * NG, smbase + (uint32_t)((ncg + 1) % 3) * STAGE_BYTES, KC);
            cp_commit();
        }
    }
}

// ---------------- decoder: out = hs @ Wdec^T, tiles 64x128 ----------------
__global__ void __launch_bounds__(256, 2)
dec_kernel(float* __restrict__ out) {
    extern __shared__ char smd[];
    const int tid = threadIdx.x;
    const int mbase = blockIdx.x * 64;
    const int pbase = blockIdx.y * 128;

    const __nv_bfloat16* ahi = g_hs_hi + (size_t)mbase * NG;
    const __nv_bfloat16* alo = g_hs_lo + (size_t)mbase * NG;
    const __nv_bfloat16* bhi = g_Wdec_hi + (size_t)pbase * NG;
    const __nv_bfloat16* blo = g_Wdec_lo + (size_t)pbase * NG;

    const int lane = tid & 31, warp = tid >> 5;
    const int wm = warp >> 2, wn = warp & 3;
    const int qa = lane >> 3, ra = lane & 7;
    const int a_row0 = wm * 32 + (qa & 1) * 8 + ra;
    const int a_col0 = (qa >> 1) * 8;
    const int qb = lane >> 3, rb = lane & 7;
    const int b_row0 = wn * 32 + (qb >> 1) * 8 + rb;
    const int b_col0 = (qb & 1) * 8;
    const uint32_t smbase = smem_u32(smd);

    load_W(bhi, blo, NG, smbase, 0);
    load_A(ahi, alo, NG, smbase, 0);
    cp_commit();
    load_W(bhi, blo, NG, smbase + STAGE_BYTES, KC);
    load_A(ahi, alo, NG, smbase + STAGE_BYTES, KC);
    cp_commit();

    float d[2][4][4] = {};
#pragma unroll 1
    for (int c = 0; c < DEC_CHUNKS; c++) {
        if (c == 1) cp_wait<0>(); else cp_wait<1>();
        __syncthreads();
        compute_chunk(smbase + (uint32_t)(c % 3) * STAGE_BYTES,
                      a_row0, a_col0, b_row0, b_col0, d);
        if (c + 2 < DEC_CHUNKS) {
            const uint32_t stn = smbase + (uint32_t)((c + 2) % 3) * STAGE_BYTES;
            load_W(bhi, blo, NG, stn, (c + 2) * KC);
            load_A(ahi, alo, NG, stn, (c + 2) * KC);
        }
        cp_commit();
    }

#pragma unroll
    for (int mb = 0; mb < 2; mb++)
#pragma unroll
        for (int nb = 0; nb < 4; nb++) {
            int row = mbase + wm * 32 + mb * 16 + (lane >> 2);
            int col = pbase + wn * 32 + nb * 8 + (lane & 3) * 2;
            *(float2*)&out[(size_t)row * NPL + col] = make_float2(d[mb][nb][0], d[mb][nb][1]);
            *(float2*)&out[(size_t)(row + 8) * NPL + col] = make_float2(d[mb][nb][2], d[mb][nb][3]);
        }
}

extern "C" void kernel_launch(void* const* d_in, const int* in_sizes, int n_in,
                              void* d_out, int out_size) {
    const float* v     = (const float*)d_in[0];
    const float* p0    = (const float*)d_in[1];
    const float* Winit = (const float*)d_in[2];
    const float* Wih   = (const float*)d_in[3];
    const float* Whh   = (const float*)d_in[4];
    const float* Wdec  = (const float*)d_in[5];
    float* out = (float*)d_out;

    cudaFuncSetAttribute(rnn_persistent, cudaFuncAttributeMaxDynamicSharedMemorySize, SMEM_BYTES);
    cudaFuncSetAttribute(dec_kernel,     cudaFuncAttributeMaxDynamicSharedMemorySize, SMEM_BYTES);

    split_whh_kernel<<<2048, 256>>>(Whh);
    split_wdec_kernel<<<512, 256>>>(Wdec);
    h0_kernel<<<64, 256>>>(p0, Winit);
    reset_kernel<<<1, 32>>>();
    rnn_persistent<<<256, 256, SMEM_BYTES>>>(v, Wih);
    dec_kernel<<<dim3(BB * SS / 64, NPL / 128), 256, SMEM_BYTES>>>(out);
}